// round 2
// baseline (speedup 1.0000x reference)
#include <cuda_runtime.h>
#include <math.h>

#define N_NODES 50000
#define N_EDGES 500000
#define EN      (N_EDGES + N_NODES)   // 550000 incl. self loops
#define D_IN    128
#define D_HID   256

// ---------------- device scratch (static globals; no allocation) -----------
__device__ int   g_deg[N_NODES];
__device__ int   g_row_ptr[N_NODES + 1];
__device__ int   g_pos[N_NODES];
__device__ int   g_col[EN];
__device__ float g_enorm[EN];
__device__ float g_dinv[N_NODES];
__device__ float g_aggx[(size_t)N_NODES * D_IN];   // layer-1 aggregated input
__device__ float g_h  [(size_t)N_NODES * D_HID];   // post-GEMM activations
__device__ float g_agg[(size_t)N_NODES * D_HID];   // aggregated activations

// ---------------- CSR construction -----------------------------------------
__global__ void k_init_deg() {
    int i = blockIdx.x * blockDim.x + threadIdx.x;
    if (i < N_NODES) g_deg[i] = 1;   // self loop contributes 1 to degree
}

__global__ void k_count(const int* __restrict__ ei) {
    int e = blockIdx.x * blockDim.x + threadIdx.x;
    if (e < N_EDGES) {
        int d = ei[N_EDGES + e];     // dst row of edge_index
        atomicAdd(&g_deg[d], 1);
    }
}

// Single-block exclusive scan of g_deg -> g_row_ptr (+ g_pos copy, + dinv).
__global__ void k_scan() {
    __shared__ int s[1024];
    const int t = threadIdx.x;
    const int CH = (N_NODES + 1023) / 1024;          // 49
    int start = t * CH;
    int end   = start + CH; if (end > N_NODES) end = N_NODES;
    if (start > N_NODES) start = N_NODES;

    int sum = 0;
    for (int i = start; i < end; i++) sum += g_deg[i];
    s[t] = sum;
    __syncthreads();
    // inclusive Hillis-Steele scan over 1024 partials
    for (int off = 1; off < 1024; off <<= 1) {
        int v = (t >= off) ? s[t - off] : 0;
        __syncthreads();
        s[t] += v;
        __syncthreads();
    }
    int prefix = (t == 0) ? 0 : s[t - 1];
    for (int i = start; i < end; i++) {
        int d = g_deg[i];
        g_row_ptr[i] = prefix;
        g_pos[i]     = prefix;
        g_dinv[i]    = rsqrtf((float)d);             // deg >= 1 always
        prefix += d;
    }
    if (t == 0) g_row_ptr[N_NODES] = s[1023];
}

__global__ void k_fill(const int* __restrict__ ei) {
    int idx = blockIdx.x * blockDim.x + threadIdx.x;
    if (idx < N_EDGES) {
        int s = ei[idx];
        int d = ei[N_EDGES + idx];
        int p = atomicAdd(&g_pos[d], 1);
        g_col[p]   = s;
        g_enorm[p] = g_dinv[s] * g_dinv[d];
    } else if (idx < EN) {
        int i = idx - N_EDGES;                       // self loop
        int p = atomicAdd(&g_pos[i], 1);
        g_col[p]   = i;
        float di = g_dinv[i];
        g_enorm[p] = di * di;
    }
}

// ---------------- aggregation: out[i] = sum_j norm * feat[col[j]] -----------
// One warp per node. D4 = row width in float4 units (32 -> 128 dims, 64 -> 256).
template <int D4>
__global__ void k_aggregate(const float* __restrict__ feat, float* __restrict__ out) {
    const int warp = blockIdx.x * (blockDim.x >> 5) + (threadIdx.x >> 5);
    const int lane = threadIdx.x & 31;
    if (warp >= N_NODES) return;

    const int rs = g_row_ptr[warp];
    const int re = g_row_ptr[warp + 1];

    float4 acc0 = make_float4(0.f, 0.f, 0.f, 0.f);
    float4 acc1 = make_float4(0.f, 0.f, 0.f, 0.f);

    for (int j = rs; j < re; j += 32) {
        int m = re - j; if (m > 32) m = 32;
        int   c = 0; float w = 0.f;
        if (lane < m) { c = g_col[j + lane]; w = g_enorm[j + lane]; }
        for (int k = 0; k < m; k++) {
            int   cc = __shfl_sync(0xffffffffu, c, k);
            float ww = __shfl_sync(0xffffffffu, w, k);
            const float4* row = reinterpret_cast<const float4*>(feat) + (size_t)cc * D4;
            float4 v = __ldg(&row[lane]);
            acc0.x = fmaf(ww, v.x, acc0.x);
            acc0.y = fmaf(ww, v.y, acc0.y);
            acc0.z = fmaf(ww, v.z, acc0.z);
            acc0.w = fmaf(ww, v.w, acc0.w);
            if (D4 == 64) {
                float4 v1 = __ldg(&row[lane + 32]);
                acc1.x = fmaf(ww, v1.x, acc1.x);
                acc1.y = fmaf(ww, v1.y, acc1.y);
                acc1.z = fmaf(ww, v1.z, acc1.z);
                acc1.w = fmaf(ww, v1.w, acc1.w);
            }
        }
    }
    float4* orow = reinterpret_cast<float4*>(out) + (size_t)warp * D4;
    orow[lane] = acc0;
    if (D4 == 64) orow[lane + 32] = acc1;
}

// ---------------- fp32 tiled GEMM: C[M,256] = A[M,K] @ W[K,256] + b ---------
// BM=BN=64, BK=16, 256 threads, 4x4 thread tile.
template <int K, bool RELU>
__global__ __launch_bounds__(256) void k_gemm(const float* __restrict__ A,
                                              const float* __restrict__ W,
                                              const float* __restrict__ bias,
                                              float* __restrict__ C) {
    __shared__ float As[16][64];
    __shared__ float Bs[16][64];

    const int tid = threadIdx.x;
    const int tx  = tid & 15;          // 0..15  (N direction, x4)
    const int ty  = tid >> 4;          // 0..15  (M direction, x4)
    const int m0  = blockIdx.y * 64;
    const int n0  = blockIdx.x * 64;

    const int a_m = tid >> 2;          // 0..63
    const int a_k = (tid & 3) * 4;     // 0,4,8,12
    const int b_k = tid >> 4;          // 0..15
    const int b_n = (tid & 15) * 4;    // 0..60
    const bool m_ok = (m0 + a_m) < N_NODES;

    float acc[4][4];
#pragma unroll
    for (int i = 0; i < 4; i++)
#pragma unroll
        for (int j = 0; j < 4; j++) acc[i][j] = 0.f;

    for (int k0 = 0; k0 < K; k0 += 16) {
        float4 av = make_float4(0.f, 0.f, 0.f, 0.f);
        if (m_ok)
            av = *reinterpret_cast<const float4*>(A + (size_t)(m0 + a_m) * K + k0 + a_k);
        As[a_k + 0][a_m] = av.x;
        As[a_k + 1][a_m] = av.y;
        As[a_k + 2][a_m] = av.z;
        As[a_k + 3][a_m] = av.w;
        float4 bv = *reinterpret_cast<const float4*>(W + (size_t)(k0 + b_k) * D_HID + n0 + b_n);
        *reinterpret_cast<float4*>(&Bs[b_k][b_n]) = bv;
        __syncthreads();
#pragma unroll
        for (int kk = 0; kk < 16; kk++) {
            float4 a = *reinterpret_cast<float4*>(&As[kk][ty * 4]);
            float4 b = *reinterpret_cast<float4*>(&Bs[kk][tx * 4]);
            float aa[4] = {a.x, a.y, a.z, a.w};
            float bb[4] = {b.x, b.y, b.z, b.w};
#pragma unroll
            for (int i = 0; i < 4; i++)
#pragma unroll
                for (int j = 0; j < 4; j++)
                    acc[i][j] = fmaf(aa[i], bb[j], acc[i][j]);
        }
        __syncthreads();
    }

    float4 bv = *reinterpret_cast<const float4*>(bias + n0 + tx * 4);
    float bb[4] = {bv.x, bv.y, bv.z, bv.w};
#pragma unroll
    for (int i = 0; i < 4; i++) {
        int m = m0 + ty * 4 + i;
        if (m < N_NODES) {
            float4 r;
            r.x = acc[i][0] + bb[0];
            r.y = acc[i][1] + bb[1];
            r.z = acc[i][2] + bb[2];
            r.w = acc[i][3] + bb[3];
            if (RELU) {
                r.x = fmaxf(r.x, 0.f); r.y = fmaxf(r.y, 0.f);
                r.z = fmaxf(r.z, 0.f); r.w = fmaxf(r.w, 0.f);
            }
            *reinterpret_cast<float4*>(C + (size_t)m * D_HID + n0 + tx * 4) = r;
        }
    }
}

// ---------------- launch ----------------------------------------------------
extern "C" void kernel_launch(void* const* d_in, const int* in_sizes, int n_in,
                              void* d_out, int out_size) {
    const float* x  = (const float*)d_in[0];
    const int*   ei = (const int*)  d_in[1];
    const float* W1 = (const float*)d_in[2];
    const float* b1 = (const float*)d_in[3];
    const float* W2 = (const float*)d_in[4];
    const float* b2 = (const float*)d_in[5];
    const float* W3 = (const float*)d_in[6];
    const float* b3 = (const float*)d_in[7];
    float* out = (float*)d_out;

    void *p_aggx, *p_h, *p_agg;
    cudaGetSymbolAddress(&p_aggx, g_aggx);
    cudaGetSymbolAddress(&p_h,    g_h);
    cudaGetSymbolAddress(&p_agg,  g_agg);
    float* aggx = (float*)p_aggx;
    float* h    = (float*)p_h;
    float* agg  = (float*)p_agg;

    // CSR build (per launch; graph-capturable, kernel launches only)
    k_init_deg<<<(N_NODES + 255) / 256, 256>>>();
    k_count   <<<(N_EDGES + 255) / 256, 256>>>(ei);
    k_scan    <<<1, 1024>>>();
    k_fill    <<<(EN + 255) / 256, 256>>>(ei);

    const int aggBlocks = (N_NODES + 7) / 8;   // 8 warps/block, 1 warp/node
    dim3 gemmGrid(D_HID / 64, (N_NODES + 63) / 64);

    // Layer 1: agg first on 128 dims (Â x) W1 + b1, relu
    k_aggregate<32><<<aggBlocks, 256>>>(x, aggx);
    k_gemm<D_IN, true><<<gemmGrid, 256>>>(aggx, W1, b1, h);

    // Layer 2
    k_aggregate<64><<<aggBlocks, 256>>>(h, agg);
    k_gemm<D_HID, true><<<gemmGrid, 256>>>(agg, W2, b2, h);

    // Layer 3 (no relu), straight to output
    k_aggregate<64><<<aggBlocks, 256>>>(h, agg);
    k_gemm<D_HID, false><<<gemmGrid, 256>>>(agg, W3, b3, out);
}

// round 5
// speedup vs baseline: 1.5438x; 1.5438x over previous
#include <cuda_runtime.h>
#include <cuda_bf16.h>
#include <cstdint>
#include <math.h>

#define N_NODES 50000
#define N_EDGES 500000
#define EN      (N_EDGES + N_NODES)   // 550000 incl. self loops
#define D_IN    128
#define D_HID   256
#define BM      128
#define BN      128
#define BK      32
#define N_CTAS  ((N_NODES + BM - 1) / BM)   // 391
#define M_PAD   (N_CTAS * BM)               // 50048

// ---------------- async-copy helpers (portable PTX, sm_80+) -----------------
__device__ __forceinline__ uint32_t smem_to_u32(const void* p) {
    uint32_t a;
    asm("{ .reg .u64 t; cvta.to.shared.u64 t, %1; cvt.u32.u64 %0, t; }" : "=r"(a) : "l"(p));
    return a;
}
__device__ __forceinline__ void cp_async16(uint32_t s, const void* g) {
    asm volatile("cp.async.cg.shared.global [%0], [%1], 16;" :: "r"(s), "l"(g));
}
__device__ __forceinline__ void cp_commit() {
    asm volatile("cp.async.commit_group;" ::: "memory");
}
template <int N>
__device__ __forceinline__ void cp_wait() {
    asm volatile("cp.async.wait_group %0;" :: "n"(N) : "memory");
}
__device__ __forceinline__ void ldsm_x4(uint32_t* r, uint32_t addr) {
    asm volatile("ldmatrix.sync.aligned.m8n8.x4.shared.b16 {%0,%1,%2,%3}, [%4];"
                 : "=r"(r[0]), "=r"(r[1]), "=r"(r[2]), "=r"(r[3]) : "r"(addr));
}
__device__ __forceinline__ void mma_bf16(float* c, const uint32_t* a, const uint32_t* b) {
    asm volatile(
        "mma.sync.aligned.m16n8k16.row.col.f32.bf16.bf16.f32 "
        "{%0,%1,%2,%3}, {%4,%5,%6,%7}, {%8,%9}, {%0,%1,%2,%3};"
        : "+f"(c[0]), "+f"(c[1]), "+f"(c[2]), "+f"(c[3])
        : "r"(a[0]), "r"(a[1]), "r"(a[2]), "r"(a[3]), "r"(b[0]), "r"(b[1]));
}

// ---------------- device scratch (static globals; no allocation) ------------
__device__ int   g_deg[N_NODES];
__device__ int   g_row_ptr[N_NODES + 1];
__device__ int   g_pos[N_NODES];
__device__ int   g_col[EN];
__device__ float g_enorm[EN];
__device__ float g_dinv[N_NODES];
__device__ __align__(16) float g_h[(size_t)N_NODES * D_HID];           // fp32 activations
__device__ __align__(16) __nv_bfloat16 g_ah[(size_t)M_PAD * D_HID];    // split-hi of agg
__device__ __align__(16) __nv_bfloat16 g_al[(size_t)M_PAD * D_HID];    // split-lo of agg
__device__ __align__(16) __nv_bfloat16 g_w1h[D_HID * D_IN];            // W^T [256,128]
__device__ __align__(16) __nv_bfloat16 g_w1l[D_HID * D_IN];
__device__ __align__(16) __nv_bfloat16 g_w2h[D_HID * D_HID];           // W^T [256,256]
__device__ __align__(16) __nv_bfloat16 g_w2l[D_HID * D_HID];
__device__ __align__(16) __nv_bfloat16 g_w3h[D_HID * D_HID];
__device__ __align__(16) __nv_bfloat16 g_w3l[D_HID * D_HID];

// ---------------- CSR construction ------------------------------------------
__global__ void k_init_deg() {
    int i = blockIdx.x * blockDim.x + threadIdx.x;
    if (i < N_NODES) g_deg[i] = 1;
}

__global__ void k_count(const int* __restrict__ ei) {
    int e = blockIdx.x * blockDim.x + threadIdx.x;
    if (e < N_EDGES) atomicAdd(&g_deg[ei[N_EDGES + e]], 1);
}

__global__ void k_scan() {
    __shared__ int s[1024];
    const int t = threadIdx.x;
    const int CH = (N_NODES + 1023) / 1024;
    int start = t * CH;
    int end = start + CH; if (end > N_NODES) end = N_NODES;
    if (start > N_NODES) start = N_NODES;
    int sum = 0;
    for (int i = start; i < end; i++) sum += g_deg[i];
    s[t] = sum;
    __syncthreads();
    for (int off = 1; off < 1024; off <<= 1) {
        int v = (t >= off) ? s[t - off] : 0;
        __syncthreads();
        s[t] += v;
        __syncthreads();
    }
    int prefix = (t == 0) ? 0 : s[t - 1];
    for (int i = start; i < end; i++) {
        int d = g_deg[i];
        g_row_ptr[i] = prefix;
        g_pos[i] = prefix;
        g_dinv[i] = rsqrtf((float)d);
        prefix += d;
    }
    if (t == 0) g_row_ptr[N_NODES] = s[1023];
}

__global__ void k_fill(const int* __restrict__ ei) {
    int idx = blockIdx.x * blockDim.x + threadIdx.x;
    if (idx < N_EDGES) {
        int s = ei[idx];
        int d = ei[N_EDGES + idx];
        int p = atomicAdd(&g_pos[d], 1);
        g_col[p] = s;
        g_enorm[p] = g_dinv[s] * g_dinv[d];
    } else if (idx < EN) {
        int i = idx - N_EDGES;
        int p = atomicAdd(&g_pos[i], 1);
        g_col[p] = i;
        float di = g_dinv[i];
        g_enorm[p] = di * di;
    }
}

// ---------------- weight split + transpose: W[K,256] -> Wt hi/lo [256,K] ----
__global__ void k_split_w(const float* __restrict__ W, int K,
                          __nv_bfloat16* __restrict__ oh, __nv_bfloat16* __restrict__ ol) {
    int idx = blockIdx.x * blockDim.x + threadIdx.x;
    if (idx < K * D_HID) {
        int k = idx / D_HID, n = idx % D_HID;
        float v = W[idx];
        __nv_bfloat16 h = __float2bfloat16(v);
        float hv = __bfloat162float(h);
        oh[(size_t)n * K + k] = h;
        ol[(size_t)n * K + k] = __float2bfloat16(v - hv);
    }
}

// ---------------- aggregation + fp32->bf16 hi/lo split ----------------------
__device__ __forceinline__ void split_store4(__nv_bfloat16* oh, __nv_bfloat16* ol,
                                             size_t off, float4 a) {
    __nv_bfloat16 hx = __float2bfloat16(a.x);
    __nv_bfloat16 hy = __float2bfloat16(a.y);
    __nv_bfloat16 hz = __float2bfloat16(a.z);
    __nv_bfloat16 hw = __float2bfloat16(a.w);
    union { __nv_bfloat162 b[2]; uint2 u; } H, L;
    H.b[0] = __halves2bfloat162(hx, hy);
    H.b[1] = __halves2bfloat162(hz, hw);
    L.b[0] = __halves2bfloat162(__float2bfloat16(a.x - __bfloat162float(hx)),
                                __float2bfloat16(a.y - __bfloat162float(hy)));
    L.b[1] = __halves2bfloat162(__float2bfloat16(a.z - __bfloat162float(hz)),
                                __float2bfloat16(a.w - __bfloat162float(hw)));
    *reinterpret_cast<uint2*>(oh + off) = H.u;
    *reinterpret_cast<uint2*>(ol + off) = L.u;
}

template <int D>   // 128 or 256
__global__ void k_agg_split(const float* __restrict__ feat,
                            __nv_bfloat16* __restrict__ oh,
                            __nv_bfloat16* __restrict__ ol) {
    const int warp = blockIdx.x * (blockDim.x >> 5) + (threadIdx.x >> 5);
    const int lane = threadIdx.x & 31;
    if (warp >= N_NODES) return;
    const int rs = g_row_ptr[warp];
    const int re = g_row_ptr[warp + 1];

    float4 acc0 = make_float4(0.f, 0.f, 0.f, 0.f);
    float4 acc1 = make_float4(0.f, 0.f, 0.f, 0.f);

    for (int j = rs; j < re; j += 32) {
        int m = re - j; if (m > 32) m = 32;
        int c = 0; float w = 0.f;
        if (lane < m) { c = g_col[j + lane]; w = g_enorm[j + lane]; }
        for (int k = 0; k < m; k++) {
            int   cc = __shfl_sync(0xffffffffu, c, k);
            float ww = __shfl_sync(0xffffffffu, w, k);
            const float4* row = reinterpret_cast<const float4*>(feat) + (size_t)cc * (D / 4);
            float4 v = __ldg(&row[lane]);
            acc0.x = fmaf(ww, v.x, acc0.x);
            acc0.y = fmaf(ww, v.y, acc0.y);
            acc0.z = fmaf(ww, v.z, acc0.z);
            acc0.w = fmaf(ww, v.w, acc0.w);
            if (D == 256) {
                float4 v1 = __ldg(&row[lane + 32]);
                acc1.x = fmaf(ww, v1.x, acc1.x);
                acc1.y = fmaf(ww, v1.y, acc1.y);
                acc1.z = fmaf(ww, v1.z, acc1.z);
                acc1.w = fmaf(ww, v1.w, acc1.w);
            }
        }
    }
    split_store4(oh, ol, (size_t)warp * D + lane * 4, acc0);
    if (D == 256) split_store4(oh, ol, (size_t)warp * D + 128 + lane * 4, acc1);
}

// ---------------- split-bf16 mma.sync GEMM ----------------------------------
// C[M,256] = Ah@Bh^T + Ah@Bl^T + Al@Bh^T + bias, B stored [N=256, K] bf16.
// CTA 256 thr, tile 128x128x32, double-buffered cp.async, warps 4(M) x 2(N),
// warp tile 32x64 via m16n8k16. SMEM rows padded to 40 bf16 (80B) ->
// conflict-free ldmatrix (80*r mod 128 covers all eight 16B banks).
#define PITCH   40                        // bf16 elements per smem row
#define STAGE_B (BM * PITCH * 2)          // 10240 bytes per operand tile
#define STAGE   (2 * STAGE_B)             // 20480 bytes per stage

template <int KP, bool RELU>
__global__ __launch_bounds__(256, 2) void k_gemm_mma(
    const __nv_bfloat16* __restrict__ Ah, const __nv_bfloat16* __restrict__ Al,
    const __nv_bfloat16* __restrict__ Bh, const __nv_bfloat16* __restrict__ Bl,
    const float* __restrict__ bias, float* __restrict__ C) {
    __shared__ __align__(128) char smem[2 * STAGE];
    const uint32_t sb = smem_to_u32(smem);
    const int tid  = threadIdx.x;
    const int wid  = tid >> 5;
    const int lane = tid & 31;
    const int wm   = wid >> 1;           // 0..3  (M)
    const int wn   = wid & 1;            // 0..1  (N)
    const int m0   = blockIdx.y * BM;
    const int n0   = blockIdx.x * BN;

    const __nv_bfloat16* Ap[3] = {Ah, Ah, Al};
    const __nv_bfloat16* Bp[3] = {Bh, Bl, Bh};
    constexpr int TP = KP / BK;          // tiles per part (4 or 8)
    constexpr int T  = 3 * TP;

    // per-thread load assignment: 2 chunks of 16B for A, 2 for B per tile
    const int c0r = tid >> 1;                  // A/B row for chunk set 0 (0..127)
    const int c0c = (tid & 1);                 // chunk col base

    float acc[2][8][4];
#pragma unroll
    for (int i = 0; i < 2; i++)
#pragma unroll
        for (int j = 0; j < 8; j++)
#pragma unroll
            for (int q = 0; q < 4; q++) acc[i][j][q] = 0.f;

    auto load_tile = [&](int buf, int t) {
        const int part = t / TP;
        const int kc   = (t % TP) * BK;
        const __nv_bfloat16* Ag = Ap[part];
        const __nv_bfloat16* Bg = Bp[part];
        const uint32_t aB = sb + buf * STAGE;
        const uint32_t bB = aB + STAGE_B;
#pragma unroll
        for (int i = 0; i < 2; i++) {
            int c   = tid + i * 256;           // 0..511
            int row = c >> 2;
            int ch  = c & 3;
            cp_async16(aB + row * 80 + ch * 16,
                       Ag + (size_t)(m0 + row) * KP + kc + ch * 8);
            cp_async16(bB + row * 80 + ch * 16,
                       Bg + (size_t)(n0 + row) * KP + kc + ch * 8);
        }
        (void)c0r; (void)c0c;
    };

    load_tile(0, 0);
    cp_commit();

    for (int t = 0; t < T; ++t) {
        if (t + 1 < T) { load_tile((t + 1) & 1, t + 1); cp_commit(); cp_wait<1>(); }
        else           { cp_wait<0>(); }
        __syncthreads();

        const uint32_t aB = sb + (t & 1) * STAGE;
        const uint32_t bB = aB + STAGE_B;
#pragma unroll
        for (int ks = 0; ks < 2; ++ks) {
            const int koff = ks * 16;
            uint32_t a[2][4];
#pragma unroll
            for (int mi = 0; mi < 2; ++mi) {
                int row = wm * 32 + mi * 16 + (lane & 15);
                uint32_t addr = aB + row * 80 + (koff + ((lane >> 4) << 3)) * 2;
                ldsm_x4(a[mi], addr);
            }
            uint32_t b[8][2];
#pragma unroll
            for (int nj = 0; nj < 4; ++nj) {
                int g = lane >> 3;
                int nl = wn * 64 + nj * 16 + ((g >> 1) << 3) + (lane & 7);
                uint32_t addr = bB + nl * 80 + (koff + ((g & 1) << 3)) * 2;
                uint32_t r[4];
                ldsm_x4(r, addr);
                b[nj * 2 + 0][0] = r[0]; b[nj * 2 + 0][1] = r[1];
                b[nj * 2 + 1][0] = r[2]; b[nj * 2 + 1][1] = r[3];
            }
#pragma unroll
            for (int mi = 0; mi < 2; ++mi)
#pragma unroll
                for (int ni = 0; ni < 8; ++ni)
                    mma_bf16(acc[mi][ni], a[mi], b[ni]);
        }
        __syncthreads();
    }

    // epilogue: bias + relu, write fp32
    const int lr = lane >> 2;
    const int lc = (lane & 3) * 2;
#pragma unroll
    for (int mi = 0; mi < 2; ++mi) {
        int rb = m0 + wm * 32 + mi * 16 + lr;
#pragma unroll
        for (int half = 0; half < 2; ++half) {
            int r = rb + half * 8;
            if (r < N_NODES) {
                float* crow = C + (size_t)r * D_HID;
#pragma unroll
                for (int ni = 0; ni < 8; ++ni) {
                    int col = n0 + wn * 64 + ni * 8 + lc;
                    float2 bv = *reinterpret_cast<const float2*>(bias + col);
                    float2 o;
                    o.x = acc[mi][ni][half * 2 + 0] + bv.x;
                    o.y = acc[mi][ni][half * 2 + 1] + bv.y;
                    if (RELU) { o.x = fmaxf(o.x, 0.f); o.y = fmaxf(o.y, 0.f); }
                    *reinterpret_cast<float2*>(crow + col) = o;
                }
            }
        }
    }
}

// ---------------- launch ----------------------------------------------------
extern "C" void kernel_launch(void* const* d_in, const int* in_sizes, int n_in,
                              void* d_out, int out_size) {
    const float* x  = (const float*)d_in[0];
    const int*   ei = (const int*)  d_in[1];
    const float* W1 = (const float*)d_in[2];
    const float* b1 = (const float*)d_in[3];
    const float* W2 = (const float*)d_in[4];
    const float* b2 = (const float*)d_in[5];
    const float* W3 = (const float*)d_in[6];
    const float* b3 = (const float*)d_in[7];
    float* out = (float*)d_out;

    void *p_h, *p_ah, *p_al, *p1h, *p1l, *p2h, *p2l, *p3h, *p3l;
    cudaGetSymbolAddress(&p_h,  g_h);
    cudaGetSymbolAddress(&p_ah, g_ah);
    cudaGetSymbolAddress(&p_al, g_al);
    cudaGetSymbolAddress(&p1h, g_w1h); cudaGetSymbolAddress(&p1l, g_w1l);
    cudaGetSymbolAddress(&p2h, g_w2h); cudaGetSymbolAddress(&p2l, g_w2l);
    cudaGetSymbolAddress(&p3h, g_w3h); cudaGetSymbolAddress(&p3l, g_w3l);
    float* h = (float*)p_h;
    __nv_bfloat16* ah = (__nv_bfloat16*)p_ah;
    __nv_bfloat16* al = (__nv_bfloat16*)p_al;

    // CSR build
    k_init_deg<<<(N_NODES + 255) / 256, 256>>>();
    k_count   <<<(N_EDGES + 255) / 256, 256>>>(ei);
    k_scan    <<<1, 1024>>>();
    k_fill    <<<(EN + 255) / 256, 256>>>(ei);

    // weight splits (transposed to [N,K] bf16 hi/lo)
    k_split_w<<<(D_IN  * D_HID + 255) / 256, 256>>>(W1, D_IN,  (__nv_bfloat16*)p1h, (__nv_bfloat16*)p1l);
    k_split_w<<<(D_HID * D_HID + 255) / 256, 256>>>(W2, D_HID, (__nv_bfloat16*)p2h, (__nv_bfloat16*)p2l);
    k_split_w<<<(D_HID * D_HID + 255) / 256, 256>>>(W3, D_HID, (__nv_bfloat16*)p3h, (__nv_bfloat16*)p3l);

    const int aggBlocks = (N_NODES + 7) / 8;   // 8 warps/block, 1 warp/node
    dim3 gemmGrid(D_HID / BN, N_CTAS);

    // Layer 1: (A_hat x) W1 + b1, relu
    k_agg_split<D_IN><<<aggBlocks, 256>>>(x, ah, al);
    k_gemm_mma<D_IN, true><<<gemmGrid, 256>>>(ah, al,
        (__nv_bfloat16*)p1h, (__nv_bfloat16*)p1l, b1, h);

    // Layer 2
    k_agg_split<D_HID><<<aggBlocks, 256>>>(h, ah, al);
    k_gemm_mma<D_HID, true><<<gemmGrid, 256>>>(ah, al,
        (__nv_bfloat16*)p2h, (__nv_bfloat16*)p2l, b2, h);

    // Layer 3 (no relu), straight to output
    k_agg_split<D_HID><<<aggBlocks, 256>>>(h, ah, al);
    k_gemm_mma<D_HID, false><<<gemmGrid, 256>>>(ah, al,
        (__nv_bfloat16*)p3h, (__nv_bfloat16*)p3l, b3, out);
}

// round 6
// speedup vs baseline: 1.6696x; 1.0814x over previous
#include <cuda_runtime.h>
#include <cuda_bf16.h>
#include <cstdint>
#include <math.h>

#define N_NODES 50000
#define N_EDGES 500000
#define EN      (N_EDGES + N_NODES)   // 550000 incl. self loops
#define D_IN    128
#define D_HID   256
#define BM      128
#define BN      128
#define BK      64
#define N_CTAS  ((N_NODES + BM - 1) / BM)   // 391
#define M_PAD   (N_CTAS * BM)               // 50048

// ---------------- async-copy helpers (portable PTX, sm_80+) -----------------
__device__ __forceinline__ uint32_t smem_to_u32(const void* p) {
    uint32_t a;
    asm("{ .reg .u64 t; cvta.to.shared.u64 t, %1; cvt.u32.u64 %0, t; }" : "=r"(a) : "l"(p));
    return a;
}
__device__ __forceinline__ void cp_async16(uint32_t s, const void* g) {
    asm volatile("cp.async.cg.shared.global [%0], [%1], 16;" :: "r"(s), "l"(g));
}
__device__ __forceinline__ void cp_commit() {
    asm volatile("cp.async.commit_group;" ::: "memory");
}
template <int N>
__device__ __forceinline__ void cp_wait() {
    asm volatile("cp.async.wait_group %0;" :: "n"(N) : "memory");
}
__device__ __forceinline__ void ldsm_x4(uint32_t* r, uint32_t addr) {
    asm volatile("ldmatrix.sync.aligned.m8n8.x4.shared.b16 {%0,%1,%2,%3}, [%4];"
                 : "=r"(r[0]), "=r"(r[1]), "=r"(r[2]), "=r"(r[3]) : "r"(addr));
}
__device__ __forceinline__ void mma_bf16(float* c, const uint32_t* a, const uint32_t* b) {
    asm volatile(
        "mma.sync.aligned.m16n8k16.row.col.f32.bf16.bf16.f32 "
        "{%0,%1,%2,%3}, {%4,%5,%6,%7}, {%8,%9}, {%0,%1,%2,%3};"
        : "+f"(c[0]), "+f"(c[1]), "+f"(c[2]), "+f"(c[3])
        : "r"(a[0]), "r"(a[1]), "r"(a[2]), "r"(a[3]), "r"(b[0]), "r"(b[1]));
}

// ---------------- device scratch (static globals; no allocation) ------------
__device__ int   g_deg[N_NODES];          // zeroed at end of every replay by k_scan
__device__ int   g_row_ptr[N_NODES + 1];
__device__ int   g_pos[N_NODES];
__device__ int   g_col[EN];
__device__ float g_enorm[EN];
__device__ float g_dinv[N_NODES];
__device__ __align__(16) float g_h[(size_t)N_NODES * D_HID];           // fp32 activations
__device__ __align__(16) __nv_bfloat16 g_ah[(size_t)M_PAD * D_HID];    // split-hi of agg
__device__ __align__(16) __nv_bfloat16 g_al[(size_t)M_PAD * D_HID];    // split-lo of agg
__device__ __align__(16) __nv_bfloat16 g_w1h[D_HID * D_IN];            // W^T [256,128]
__device__ __align__(16) __nv_bfloat16 g_w1l[D_HID * D_IN];
__device__ __align__(16) __nv_bfloat16 g_w2h[D_HID * D_HID];           // W^T [256,256]
__device__ __align__(16) __nv_bfloat16 g_w2l[D_HID * D_HID];
__device__ __align__(16) __nv_bfloat16 g_w3h[D_HID * D_HID];
__device__ __align__(16) __nv_bfloat16 g_w3l[D_HID * D_HID];

// ---------------- CSR + weight split (fused launch 1) ------------------------
// blocks [0, edge range): degree count; tail blocks: weight split/transpose.
#define W1_ELEMS (D_IN * D_HID)
#define W23_ELEMS (D_HID * D_HID)
#define SPLIT_ELEMS (W1_ELEMS + 2 * W23_ELEMS)   // 163840

__device__ __forceinline__ void split_one(const float* W, int K, int idx,
                                          __nv_bfloat16* oh, __nv_bfloat16* ol) {
    int k = idx / D_HID, n = idx % D_HID;
    float v = W[idx];
    __nv_bfloat16 h = __float2bfloat16(v);
    oh[(size_t)n * K + k] = h;
    ol[(size_t)n * K + k] = __float2bfloat16(v - __bfloat162float(h));
}

__global__ void k_count_split(const int* __restrict__ ei,
                              const float* __restrict__ W1,
                              const float* __restrict__ W2,
                              const float* __restrict__ W3) {
    int idx = blockIdx.x * blockDim.x + threadIdx.x;
    if (idx < N_EDGES) {
        atomicAdd(&g_deg[ei[N_EDGES + idx]], 1);
        return;
    }
    int j = idx - N_EDGES;
    if (j < W1_ELEMS) {
        split_one(W1, D_IN, j, g_w1h, g_w1l);
    } else if (j < W1_ELEMS + W23_ELEMS) {
        split_one(W2, D_HID, j - W1_ELEMS, g_w2h, g_w2l);
    } else if (j < SPLIT_ELEMS) {
        split_one(W3, D_HID, j - W1_ELEMS - W23_ELEMS, g_w3h, g_w3l);
    }
}

// Single-block scan. Degree = g_deg[i] + 1 (self loop). Zeroes g_deg for the
// next graph replay (deterministic: every execution starts from zeroed g_deg).
__global__ void k_scan() {
    __shared__ int s[1024];
    const int t = threadIdx.x;
    const int CH = (N_NODES + 1023) / 1024;
    int start = t * CH;
    int end = start + CH; if (end > N_NODES) end = N_NODES;
    if (start > N_NODES) start = N_NODES;
    int sum = 0;
#pragma unroll 4
    for (int i = start; i < end; i++) sum += g_deg[i] + 1;
    s[t] = sum;
    __syncthreads();
    for (int off = 1; off < 1024; off <<= 1) {
        int v = (t >= off) ? s[t - off] : 0;
        __syncthreads();
        s[t] += v;
        __syncthreads();
    }
    int prefix = (t == 0) ? 0 : s[t - 1];
    for (int i = start; i < end; i++) {
        int d = g_deg[i] + 1;
        g_deg[i] = 0;                       // reset for next replay
        g_row_ptr[i] = prefix;
        g_pos[i] = prefix;
        g_dinv[i] = rsqrtf((float)d);
        prefix += d;
    }
    if (t == 0) g_row_ptr[N_NODES] = s[1023];
}

__global__ void k_fill(const int* __restrict__ ei) {
    int idx = blockIdx.x * blockDim.x + threadIdx.x;
    if (idx < N_EDGES) {
        int s = ei[idx];
        int d = ei[N_EDGES + idx];
        int p = atomicAdd(&g_pos[d], 1);
        g_col[p] = s;
        g_enorm[p] = g_dinv[s] * g_dinv[d];
    } else if (idx < EN) {
        int i = idx - N_EDGES;
        int p = atomicAdd(&g_pos[i], 1);
        g_col[p] = i;
        float di = g_dinv[i];
        g_enorm[p] = di * di;
    }
}

// ---------------- aggregation + fp32->bf16 hi/lo split ----------------------
__device__ __forceinline__ void split_store4(__nv_bfloat16* oh, __nv_bfloat16* ol,
                                             size_t off, float4 a) {
    __nv_bfloat16 hx = __float2bfloat16(a.x);
    __nv_bfloat16 hy = __float2bfloat16(a.y);
    __nv_bfloat16 hz = __float2bfloat16(a.z);
    __nv_bfloat16 hw = __float2bfloat16(a.w);
    union { __nv_bfloat162 b[2]; uint2 u; } H, L;
    H.b[0] = __halves2bfloat162(hx, hy);
    H.b[1] = __halves2bfloat162(hz, hw);
    L.b[0] = __halves2bfloat162(__float2bfloat16(a.x - __bfloat162float(hx)),
                                __float2bfloat16(a.y - __bfloat162float(hy)));
    L.b[1] = __halves2bfloat162(__float2bfloat16(a.z - __bfloat162float(hz)),
                                __float2bfloat16(a.w - __bfloat162float(hw)));
    *reinterpret_cast<uint2*>(oh + off) = H.u;
    *reinterpret_cast<uint2*>(ol + off) = L.u;
}

template <int D>   // 128 or 256
__global__ __launch_bounds__(256) void k_agg_split(
        const float* __restrict__ feat,
        __nv_bfloat16* __restrict__ oh,
        __nv_bfloat16* __restrict__ ol) {
    const int warp = blockIdx.x * (blockDim.x >> 5) + (threadIdx.x >> 5);
    const int lane = threadIdx.x & 31;
    if (warp >= N_NODES) return;
    const int rs = g_row_ptr[warp];
    const int re = g_row_ptr[warp + 1];

    float4 acc0 = make_float4(0.f, 0.f, 0.f, 0.f);
    float4 acc1 = make_float4(0.f, 0.f, 0.f, 0.f);

    for (int j = rs; j < re; j += 32) {
        int m = re - j; if (m > 32) m = 32;
        int c = 0; float w = 0.f;
        if (lane < m) { c = g_col[j + lane]; w = g_enorm[j + lane]; }
        for (int k = 0; k < m; k++) {
            int   cc = __shfl_sync(0xffffffffu, c, k);
            float ww = __shfl_sync(0xffffffffu, w, k);
            const float4* row = reinterpret_cast<const float4*>(feat) + (size_t)cc * (D / 4);
            float4 v = __ldg(&row[lane]);
            acc0.x = fmaf(ww, v.x, acc0.x);
            acc0.y = fmaf(ww, v.y, acc0.y);
            acc0.z = fmaf(ww, v.z, acc0.z);
            acc0.w = fmaf(ww, v.w, acc0.w);
            if (D == 256) {
                float4 v1 = __ldg(&row[lane + 32]);
                acc1.x = fmaf(ww, v1.x, acc1.x);
                acc1.y = fmaf(ww, v1.y, acc1.y);
                acc1.z = fmaf(ww, v1.z, acc1.z);
                acc1.w = fmaf(ww, v1.w, acc1.w);
            }
        }
    }
    split_store4(oh, ol, (size_t)warp * D + lane * 4, acc0);
    if (D == 256) split_store4(oh, ol, (size_t)warp * D + 128 + lane * 4, acc1);
}

// ---------------- split-bf16 mma.sync GEMM ----------------------------------
// C[M,256] = Ah@Bh^T + Ah@Bl^T + Al@Bh^T + bias, B stored [N=256, K] bf16.
// CTA 256 thr, tile 128x128x64, double-buffered cp.async (2 stages x 32 KB,
// dynamic SMEM), SW128 swizzle (128B rows), warps 4(M) x 2(N), warp tile
// 32x64 via m16n8k16.
#define STAGE_A 16384                     // 128 rows x 128 B
#define STAGE   32768                     // A + B per stage
#define SMEM_DYN (2 * STAGE)              // 65536

template <int KP, bool RELU>
__global__ __launch_bounds__(256, 2) void k_gemm_mma(
    const __nv_bfloat16* __restrict__ Ah, const __nv_bfloat16* __restrict__ Al,
    const __nv_bfloat16* __restrict__ Bh, const __nv_bfloat16* __restrict__ Bl,
    const float* __restrict__ bias, float* __restrict__ C) {
    extern __shared__ __align__(128) char smem[];
    const uint32_t sb = smem_to_u32(smem);
    const int tid  = threadIdx.x;
    const int wid  = tid >> 5;
    const int lane = tid & 31;
    const int wm   = wid >> 1;           // 0..3  (M)
    const int wn   = wid & 1;            // 0..1  (N)
    const int m0   = blockIdx.y * BM;
    const int n0   = blockIdx.x * BN;

    const __nv_bfloat16* Ap[3] = {Ah, Ah, Al};
    const __nv_bfloat16* Bp[3] = {Bh, Bl, Bh};
    constexpr int TP = KP / BK;          // tiles per part (2 or 4)
    constexpr int T  = 3 * TP;

    float acc[2][8][4];
#pragma unroll
    for (int i = 0; i < 2; i++)
#pragma unroll
        for (int j = 0; j < 8; j++)
#pragma unroll
            for (int q = 0; q < 4; q++) acc[i][j][q] = 0.f;

    auto load_tile = [&](int buf, int t) {
        const int part = t / TP;
        const int kc   = (t % TP) * BK;
        const __nv_bfloat16* Ag = Ap[part];
        const __nv_bfloat16* Bg = Bp[part];
        const uint32_t aB = sb + buf * STAGE;
        const uint32_t bB = aB + STAGE_A;
        // 1024 chunks of 16B per operand; 4 A + 4 B per thread
#pragma unroll
        for (int i = 0; i < 4; ++i) {
            int c   = tid + i * 256;           // 0..1023
            int row = c >> 3;
            int ch  = c & 7;
            uint32_t sw = (uint32_t)(ch ^ (row & 7)) << 4;
            cp_async16(aB + row * 128 + sw,
                       Ag + (size_t)(m0 + row) * KP + kc + ch * 8);
            cp_async16(bB + row * 128 + sw,
                       Bg + (size_t)(n0 + row) * KP + kc + ch * 8);
        }
    };

    load_tile(0, 0);
    cp_commit();

    for (int t = 0; t < T; ++t) {
        if (t + 1 < T) { load_tile((t + 1) & 1, t + 1); cp_commit(); cp_wait<1>(); }
        else           { cp_wait<0>(); }
        __syncthreads();

        const uint32_t aB = sb + (t & 1) * STAGE;
        const uint32_t bB = aB + STAGE_A;
#pragma unroll
        for (int ks = 0; ks < 4; ++ks) {
            uint32_t a[2][4];
#pragma unroll
            for (int mi = 0; mi < 2; ++mi) {
                int row = wm * 32 + mi * 16 + (lane & 15);
                uint32_t chunk = (uint32_t)((ks << 1) + (lane >> 4));
                uint32_t addr = aB + row * 128 + ((chunk ^ (row & 7)) << 4);
                ldsm_x4(a[mi], addr);
            }
            uint32_t b[8][2];
#pragma unroll
            for (int nj = 0; nj < 4; ++nj) {
                int g = lane >> 3;
                int nl = wn * 64 + nj * 16 + ((g >> 1) << 3) + (lane & 7);
                uint32_t chunk = (uint32_t)((ks << 1) + (g & 1));
                uint32_t addr = bB + nl * 128 + ((chunk ^ (nl & 7)) << 4);
                uint32_t r[4];
                ldsm_x4(r, addr);
                b[nj * 2 + 0][0] = r[0]; b[nj * 2 + 0][1] = r[1];
                b[nj * 2 + 1][0] = r[2]; b[nj * 2 + 1][1] = r[3];
            }
#pragma unroll
            for (int mi = 0; mi < 2; ++mi)
#pragma unroll
                for (int ni = 0; ni < 8; ++ni)
                    mma_bf16(acc[mi][ni], a[mi], b[ni]);
        }
        __syncthreads();
    }

    // epilogue: bias + relu, write fp32
    const int lr = lane >> 2;
    const int lc = (lane & 3) * 2;
#pragma unroll
    for (int mi = 0; mi < 2; ++mi) {
        int rb = m0 + wm * 32 + mi * 16 + lr;
#pragma unroll
        for (int half = 0; half < 2; ++half) {
            int r = rb + half * 8;
            if (r < N_NODES) {
                float* crow = C + (size_t)r * D_HID;
#pragma unroll
                for (int ni = 0; ni < 8; ++ni) {
                    int col = n0 + wn * 64 + ni * 8 + lc;
                    float2 bv = *reinterpret_cast<const float2*>(bias + col);
                    float2 o;
                    o.x = acc[mi][ni][half * 2 + 0] + bv.x;
                    o.y = acc[mi][ni][half * 2 + 1] + bv.y;
                    if (RELU) { o.x = fmaxf(o.x, 0.f); o.y = fmaxf(o.y, 0.f); }
                    *reinterpret_cast<float2*>(crow + col) = o;
                }
            }
        }
    }
}

// ---------------- launch ----------------------------------------------------
extern "C" void kernel_launch(void* const* d_in, const int* in_sizes, int n_in,
                              void* d_out, int out_size) {
    const float* x  = (const float*)d_in[0];
    const int*   ei = (const int*)  d_in[1];
    const float* W1 = (const float*)d_in[2];
    const float* b1 = (const float*)d_in[3];
    const float* W2 = (const float*)d_in[4];
    const float* b2 = (const float*)d_in[5];
    const float* W3 = (const float*)d_in[6];
    const float* b3 = (const float*)d_in[7];
    float* out = (float*)d_out;

    cudaFuncSetAttribute(k_gemm_mma<D_IN,  true >, cudaFuncAttributeMaxDynamicSharedMemorySize, SMEM_DYN);
    cudaFuncSetAttribute(k_gemm_mma<D_HID, true >, cudaFuncAttributeMaxDynamicSharedMemorySize, SMEM_DYN);
    cudaFuncSetAttribute(k_gemm_mma<D_HID, false>, cudaFuncAttributeMaxDynamicSharedMemorySize, SMEM_DYN);

    void *p_h, *p_ah, *p_al, *p1h, *p1l, *p2h, *p2l, *p3h, *p3l;
    cudaGetSymbolAddress(&p_h,  g_h);
    cudaGetSymbolAddress(&p_ah, g_ah);
    cudaGetSymbolAddress(&p_al, g_al);
    cudaGetSymbolAddress(&p1h, g_w1h); cudaGetSymbolAddress(&p1l, g_w1l);
    cudaGetSymbolAddress(&p2h, g_w2h); cudaGetSymbolAddress(&p2l, g_w2l);
    cudaGetSymbolAddress(&p3h, g_w3h); cudaGetSymbolAddress(&p3l, g_w3l);
    float* h = (float*)p_h;
    __nv_bfloat16* ah = (__nv_bfloat16*)p_ah;
    __nv_bfloat16* al = (__nv_bfloat16*)p_al;

    // 1) fused degree count + weight split   2) scan (+deg reset)   3) fill
    k_count_split<<<(N_EDGES + SPLIT_ELEMS + 255) / 256, 256>>>(ei, W1, W2, W3);
    k_scan<<<1, 1024>>>();
    k_fill<<<(EN + 255) / 256, 256>>>(ei);

    const int aggBlocks = (N_NODES + 7) / 8;   // 8 warps/block, 1 warp/node
    dim3 gemmGrid(D_HID / BN, N_CTAS);

    // Layer 1: (A_hat x) W1 + b1, relu       (agg1 = 4th launch -> ncu capture)
    k_agg_split<D_IN><<<aggBlocks, 256>>>(x, ah, al);
    k_gemm_mma<D_IN, true><<<gemmGrid, 256, SMEM_DYN>>>(ah, al,
        (__nv_bfloat16*)p1h, (__nv_bfloat16*)p1l, b1, h);

    // Layer 2
    k_agg_split<D_HID><<<aggBlocks, 256>>>(h, ah, al);
    k_gemm_mma<D_HID, true><<<gemmGrid, 256, SMEM_DYN>>>(ah, al,
        (__nv_bfloat16*)p2h, (__nv_bfloat16*)p2l, b2, h);

    // Layer 3 (no relu), straight to output
    k_agg_split<D_HID><<<aggBlocks, 256>>>(h, ah, al);
    k_gemm_mma<D_HID, false><<<gemmGrid, 256, SMEM_DYN>>>(ah, al,
        (__nv_bfloat16*)p3h, (__nv_bfloat16*)p3l, b3, out);
}